// round 17
// baseline (speedup 1.0000x reference)
#include <cuda_runtime.h>
#include <cuda_bf16.h>
#include <cstdint>
#include <cstddef>

// Problem constants (fixed-shape problem)
#define NPTS   400000
#define CIN    32
#define COUT   32
#define KTAPS  27

#define BLOCK1 128          // 4 warps
#define WARPS1 4
#define PW     32           // points per warp
#define PTSBLK (WARPS1*PW)  // 128 points per block
#define NBLK1  (NPTS/PTSBLK) // 3125 exactly

#define TOTAL4 (NPTS*COUT/4)
#define NBLK3  (TOTAL4/256)

// Scratch (static device memory — no allocations)
__device__ float g_conv[(size_t)NPTS * COUT];
__device__ float g_part[(size_t)NBLK1 * 64];
__device__ float g_coef[64];
__device__ int   g_maskmode;   // 0 = uint8 mask, 1 = int32 mask

__device__ __forceinline__ void cp_async16(unsigned int smem_addr, const void* gptr) {
    asm volatile("cp.async.cg.shared.global [%0], [%1], 16;" :: "r"(smem_addr), "l"(gptr));
}
__device__ __forceinline__ void cp_commit() {
    asm volatile("cp.async.commit_group;");
}
__device__ __forceinline__ void cp_wait1() {
    asm volatile("cp.async.wait_group 1;");
}

// ---------------------------------------------------------------------------
// K0: detect storage width of nbr_mask (int32 {0,1} vs packed uint8 bools)
// ---------------------------------------------------------------------------
__global__ void detect_mask_kernel(const unsigned int* __restrict__ m)
{
    __shared__ int found;
    if (threadIdx.x == 0) found = 0;
    __syncthreads();
    int f = 0;
    for (int i = threadIdx.x; i < 4096; i += blockDim.x)
        if (m[i] > 1u) f = 1;
    if (f) atomicOr(&found, 1);
    __syncthreads();
    if (threadIdx.x == 0) g_maskmode = found ? 0 : 1;
}

// ---------------------------------------------------------------------------
// K1: gather-conv with cp.async tap-level pipelining.
// lane = c_out; warp owns 32 points. While computing tap k from buffer
// (k&1), tap k+1's valid rows are staged asynchronously (LDGSTS, register-
// bypass) into buffer (~k&1): one commit_group per tap, wait_group 1 before
// compute. Each lane stages its own valid row (8 x cp.async 16B), so any
// nv<=32 fits one shot (no chunk loop; center tap nv=32 included). Valid-
// point enumeration stays warp-uniform via __fns (no per-point BSSY).
// ---------------------------------------------------------------------------
__global__ __launch_bounds__(BLOCK1)
void conv_kernel(const float* __restrict__ feat,
                 const float* __restrict__ wglob,
                 const int*   __restrict__ nidx,
                 const unsigned char* __restrict__ nmask8,
                 const int*   __restrict__ nmask32,
                 float* __restrict__ convout,
                 float* __restrict__ partials)
{
    // sacc[point_in_block][lane]: each thread exclusively owns column lane.
    __shared__ float sacc[PTSBLK * 32];
    __shared__ __align__(16) float4 fs[WARPS1][2][32][8];  // ping-pong, 32 rows
    __shared__ float red[2][WARPS1][COUT];

    const int tid  = threadIdx.x;
    const int wid  = tid >> 5;
    const int lane = tid & 31;
    const int n0   = blockIdx.x * PTSBLK + wid * PW;
    const int maskmode = g_maskmode;

#pragma unroll
    for (int p = 0; p < PW; p++) sacc[(wid * PW + p) * 32 + lane] = 0.0f;

    // meta for tap 0
    bool mv;  int idxv;
    {
        const size_t j = (size_t)(n0 + lane);
        mv   = maskmode ? (nmask32[j] != 0) : (nmask8[j] != 0);
        idxv = nidx[j];
    }
    unsigned vm_cur = __ballot_sync(0xffffffffu, mv);
    // prologue: stage tap 0 into buf 0
    {
        const int nv = __popc(vm_cur);
        const unsigned pns = __fns(vm_cur, 0, lane + 1);
        const int gi = __shfl_sync(0xffffffffu, idxv, (int)(pns & 31u));
        if (lane < nv) {
            const float* src = feat + (size_t)gi * CIN;
            unsigned int dst = (unsigned int)__cvta_generic_to_shared(&fs[wid][0][lane][0]);
#pragma unroll
            for (int j = 0; j < 8; j++) cp_async16(dst + j * 16, src + j * 4);
        }
        cp_commit();
    }
    // meta for tap 1
    if (KTAPS > 1) {
        const size_t j = (size_t)1 * NPTS + (n0 + lane);
        mv   = maskmode ? (nmask32[j] != 0) : (nmask8[j] != 0);
        idxv = nidx[j];
    }

    for (int k = 0; k < KTAPS; k++) {
        unsigned vm_next = 0u;
        if (k + 1 < KTAPS) {
            vm_next = __ballot_sync(0xffffffffu, mv);
            const int idx_next = idxv;
            // prefetch meta for tap k+2
            if (k + 2 < KTAPS) {
                const size_t j = (size_t)(k + 2) * NPTS + (n0 + lane);
                mv   = maskmode ? (nmask32[j] != 0) : (nmask8[j] != 0);
                idxv = nidx[j];
            }
            // stage tap k+1 into buffer (k+1)&1
            const int nv = __popc(vm_next);
            const unsigned pns = __fns(vm_next, 0, lane + 1);
            const int gi = __shfl_sync(0xffffffffu, idx_next, (int)(pns & 31u));
            if (lane < nv) {
                const float* src = feat + (size_t)gi * CIN;
                unsigned int dst = (unsigned int)__cvta_generic_to_shared(&fs[wid][(k + 1) & 1][lane][0]);
#pragma unroll
                for (int j = 0; j < 8; j++) cp_async16(dst + j * 16, src + j * 4);
            }
        }
        cp_commit();          // one group per tap (possibly empty) — keeps accounting fixed
        cp_wait1();           // tap k's group complete (k+1's may remain outstanding)
        __syncwarp();

        if (vm_cur) {
            // weight column for tap k: w[k][ci][lane] (coalesced, L1-hot)
            const float* wk = wglob + k * (CIN * COUT) + lane;
            float wr[CIN];
#pragma unroll
            for (int ci = 0; ci < CIN; ci++) wr[ci] = __ldg(wk + ci * COUT);

            const int nvc = __popc(vm_cur);
            const float4* bufk = &fs[wid][k & 1][0][0];
#pragma unroll 1
            for (int s = 0; s < nvc; s++) {
                const int p = (int)__fns(vm_cur, 0, s + 1);
                const float4* fq = bufk + s * 8;
                const float4 q0 = fq[0], q1 = fq[1], q2 = fq[2], q3 = fq[3];
                const float4 q4 = fq[4], q5 = fq[5], q6 = fq[6], q7 = fq[7];
                float t0 = 0.f, t1 = 0.f, t2 = 0.f, t3 = 0.f;
                t0 = fmaf(q0.x, wr[ 0], t0); t1 = fmaf(q0.y, wr[ 1], t1);
                t2 = fmaf(q0.z, wr[ 2], t2); t3 = fmaf(q0.w, wr[ 3], t3);
                t0 = fmaf(q1.x, wr[ 4], t0); t1 = fmaf(q1.y, wr[ 5], t1);
                t2 = fmaf(q1.z, wr[ 6], t2); t3 = fmaf(q1.w, wr[ 7], t3);
                t0 = fmaf(q2.x, wr[ 8], t0); t1 = fmaf(q2.y, wr[ 9], t1);
                t2 = fmaf(q2.z, wr[10], t2); t3 = fmaf(q2.w, wr[11], t3);
                t0 = fmaf(q3.x, wr[12], t0); t1 = fmaf(q3.y, wr[13], t1);
                t2 = fmaf(q3.z, wr[14], t2); t3 = fmaf(q3.w, wr[15], t3);
                t0 = fmaf(q4.x, wr[16], t0); t1 = fmaf(q4.y, wr[17], t1);
                t2 = fmaf(q4.z, wr[18], t2); t3 = fmaf(q4.w, wr[19], t3);
                t0 = fmaf(q5.x, wr[20], t0); t1 = fmaf(q5.y, wr[21], t1);
                t2 = fmaf(q5.z, wr[22], t2); t3 = fmaf(q5.w, wr[23], t3);
                t0 = fmaf(q6.x, wr[24], t0); t1 = fmaf(q6.y, wr[25], t1);
                t2 = fmaf(q6.z, wr[26], t2); t3 = fmaf(q6.w, wr[27], t3);
                t0 = fmaf(q7.x, wr[28], t0); t1 = fmaf(q7.y, wr[29], t1);
                t2 = fmaf(q7.z, wr[30], t2); t3 = fmaf(q7.w, wr[31], t3);
                const float dot = (t0 + t1) + (t2 + t3);
                sacc[(wid * PW + p) * 32 + lane] += dot;   // exclusive slot
            }
        }
        vm_cur = vm_next;
    }

    // write conv output (coalesced) + per-block partial sums for batchnorm
    float s = 0.0f, s2 = 0.0f;
#pragma unroll
    for (int p = 0; p < PW; p++) {
        const float v = sacc[(wid * PW + p) * 32 + lane];
        convout[(size_t)(n0 + p) * COUT + lane] = v;
        s  += v;
        s2 += v * v;
    }
    red[0][wid][lane] = s;
    red[1][wid][lane] = s2;
    __syncthreads();
    if (wid == 0) {
        float a = 0.0f, b = 0.0f;
#pragma unroll
        for (int w = 0; w < WARPS1; w++) { a += red[0][w][lane]; b += red[1][w][lane]; }
        partials[(size_t)blockIdx.x * 64 + lane]      = a;
        partials[(size_t)blockIdx.x * 64 + 32 + lane] = b;
    }
}

// ---------------------------------------------------------------------------
// K2: reduce partials -> per-channel scale/shift (deterministic, single block)
// ---------------------------------------------------------------------------
__global__ __launch_bounds__(1024)
void stats_kernel(const float* __restrict__ part,
                  const float* __restrict__ gamma,
                  const float* __restrict__ beta,
                  float* __restrict__ coef)
{
    const int t = threadIdx.x;
    const int j = t & 63;
    const int g = t >> 6;
    float s = 0.0f;
    for (int i = g; i < NBLK1; i += 16) s += part[(size_t)i * 64 + j];
    __shared__ float sm[16][64];
    sm[g][j] = s;
    __syncthreads();
    if (t < 64) {
        float tot = 0.0f;
#pragma unroll
        for (int r = 0; r < 16; r++) tot += sm[r][t];
        sm[0][t] = tot;
    }
    __syncthreads();
    if (t < 32) {
        const float invN  = 1.0f / (float)NPTS;
        const float mean  = sm[0][t] * invN;
        const float ex2   = sm[0][32 + t] * invN;
        const float var   = ex2 - mean * mean;
        const float scale = gamma[t] * rsqrtf(var + 1e-5f);
        coef[t]      = scale;
        coef[32 + t] = beta[t] - mean * scale;
    }
}

// ---------------------------------------------------------------------------
// K3: fused normalize + ReLU (vectorized float4)
// ---------------------------------------------------------------------------
__global__ __launch_bounds__(256)
void norm_kernel(const float* __restrict__ conv,
                 const float* __restrict__ coef,
                 float* __restrict__ out)
{
    const int i = blockIdx.x * 256 + threadIdx.x;
    if (i < TOTAL4) {
        float4 v = ((const float4*)conv)[i];
        const int q = i & 7;
        const float4 sc = ((const float4*)coef)[q];
        const float4 sh = ((const float4*)(coef + 32))[q];
        v.x = fmaxf(fmaf(v.x, sc.x, sh.x), 0.0f);
        v.y = fmaxf(fmaf(v.y, sc.y, sh.y), 0.0f);
        v.z = fmaxf(fmaf(v.z, sc.z, sh.z), 0.0f);
        v.w = fmaxf(fmaf(v.w, sc.w, sh.w), 0.0f);
        ((float4*)out)[i] = v;
    }
}

// ---------------------------------------------------------------------------
extern "C" void kernel_launch(void* const* d_in, const int* in_sizes, int n_in,
                              void* d_out, int out_size)
{
    const float* feat  = (const float*)d_in[0];
    const float* w     = (const float*)d_in[1];
    const float* gamma = (const float*)d_in[2];
    const float* beta  = (const float*)d_in[3];
    const int*   nidx  = (const int*)d_in[4];
    const void*  nmask = d_in[5];
    float* out = (float*)d_out;

    float* conv;  cudaGetSymbolAddress((void**)&conv,  g_conv);
    float* part;  cudaGetSymbolAddress((void**)&part,  g_part);
    float* coef;  cudaGetSymbolAddress((void**)&coef,  g_coef);

    detect_mask_kernel<<<1, 256>>>((const unsigned int*)nmask);
    conv_kernel<<<NBLK1, BLOCK1>>>(feat, w, nidx,
                                   (const unsigned char*)nmask,
                                   (const int*)nmask,
                                   conv, part);
    stats_kernel<<<1, 1024>>>(part, gamma, beta, coef);
    norm_kernel<<<NBLK3, 256>>>(conv, coef, out);
}